// round 6
// baseline (speedup 1.0000x reference)
#include <cuda_runtime.h>
#include <cuda_bf16.h>
#include <cstdint>
#include <math.h>

// ---------------------------------------------------------------------------
// QAttention round 6: HMMA conv with cp.async double-buffered pipeline, N=256.
//   P1 prep_x: transpose x -> xt_hi/xt_lo [b][s][c] bf16 (+zero scratch)
//   P2 expand Hamilton blocks -> full weights
//   P3 weff_o: Weff = Wdw_tap @ Wqkv -> bf16 hi/lo [o][tap*128+c]; tb fold
//   P4 conv_mma: implicit-GEMM 3x3 conv, mma.sync bf16 hi/lo 3-pass,
//      2-stage LDGSTS pipeline, CTA tile M128 x N256 (2 rows)
//   P5.. attention tail
// ---------------------------------------------------------------------------

#define SPATIAL 16384
typedef unsigned long long u64;

// ------------------------- mma.sync helpers --------------------------------
__device__ __forceinline__ uint32_t smem_to_u32(const void* p) {
    uint32_t a;
    asm("{ .reg .u64 t; cvta.to.shared.u64 t, %1; cvt.u32.u64 %0, t; }"
        : "=r"(a) : "l"(p));
    return a;
}
__device__ __forceinline__ void ldsm4(uint32_t* r, uint32_t addr) {
    asm volatile("ldmatrix.sync.aligned.m8n8.x4.shared.b16 {%0,%1,%2,%3}, [%4];"
                 : "=r"(r[0]), "=r"(r[1]), "=r"(r[2]), "=r"(r[3]) : "r"(addr));
}
__device__ __forceinline__ void mma_bf16(float* d, const uint32_t* a,
                                         const uint32_t* b) {
    asm volatile(
        "mma.sync.aligned.m16n8k16.row.col.f32.bf16.bf16.f32 "
        "{%0,%1,%2,%3}, {%4,%5,%6,%7}, {%8,%9}, {%0,%1,%2,%3};"
        : "+f"(d[0]), "+f"(d[1]), "+f"(d[2]), "+f"(d[3])
        : "r"(a[0]), "r"(a[1]), "r"(a[2]), "r"(a[3]), "r"(b[0]), "r"(b[1]));
}
__device__ __forceinline__ uint32_t sw_addr(uint32_t base, int row, int unit) {
    return base + row * 128 + (((unit) ^ (row & 7)) << 4);
}
__device__ __forceinline__ void cp_async16(uint32_t saddr, const void* gptr,
                                           uint32_t bytes) {
    asm volatile("cp.async.cg.shared.global [%0], [%1], 16, %2;"
                 :: "r"(saddr), "l"(gptr), "r"(bytes) : "memory");
}
#define CP_COMMIT() asm volatile("cp.async.commit_group;" ::: "memory")
#define CP_WAIT1()  asm volatile("cp.async.wait_group 1;" ::: "memory")
#define CP_WAIT0()  asm volatile("cp.async.wait_group 0;" ::: "memory")

// ------------------------- f32x2 helpers (final_gemm) ----------------------
__device__ __forceinline__ u64 pack2(float lo, float hi) {
    u64 r; asm("mov.b64 %0,{%1,%2};" : "=l"(r) : "f"(lo), "f"(hi)); return r;
}
__device__ __forceinline__ float2 unpack2(u64 v) {
    float2 f; asm("mov.b64 {%0,%1},%2;" : "=f"(f.x), "=f"(f.y) : "l"(v)); return f;
}
__device__ __forceinline__ u64 fma2(u64 a, u64 b, u64 c) {
    u64 d; asm("fma.rn.f32x2 %0,%1,%2,%3;" : "=l"(d) : "l"(a), "l"(b), "l"(c)); return d;
}

// ------------------------- device scratch ----------------------------------
__device__ float g_Wqkv[384 * 128];
__device__ float g_Wdw[384 * 384 * 9];
__device__ float g_Wpo[128 * 128];
__device__ __nv_bfloat16 g_WeffHi[384 * 1152];   // [o][tap*128+c]
__device__ __nv_bfloat16 g_WeffLo[384 * 1152];
__device__ float g_tb[384 * 9];
__device__ __nv_bfloat16 g_xt_hi[2 * SPATIAL * 128];  // [b][s][c]
__device__ __nv_bfloat16 g_xt_lo[2 * SPATIAL * 128];
__device__ float g_qkv2[2 * 384 * SPATIAL];
__device__ float g_attnP[2 * 4 * 32 * 32];
__device__ float g_attn[2 * 4 * 32 * 32];
__device__ float g_inv[2 * 2 * 128];
__device__ float g_ss[2 * 256];
__device__ float g_M2[2 * 128 * 128];

// ---------------------------------------------------------------------------
// P1: transpose x to [b][s][c] bf16 hi/lo; block(0,0) also zeros scratch.
// ---------------------------------------------------------------------------
__global__ void prep_x(const float* __restrict__ X) {
    __shared__ float t[128][33];
    int s0 = blockIdx.x * 32;
    int b  = blockIdx.y;
    int tid = threadIdx.x;

    if (blockIdx.x == 0 && b == 0) {
        for (int i = tid; i < 8192; i += 256) g_attnP[i] = 0.f;
        for (int i = tid; i < 512; i += 256) g_ss[i] = 0.f;
    }
    for (int i = tid; i < 4096; i += 256) {
        int c = i >> 5, s = i & 31;
        t[c][s] = X[((size_t)(b * 128 + c)) * SPATIAL + s0 + s];
    }
    __syncthreads();
    for (int i = tid; i < 4096; i += 256) {
        int s = i >> 7, c = i & 127;
        float v = t[c][s];
        __nv_bfloat16 hi = __float2bfloat16(v);
        float vlo = v - __bfloat162float(hi);
        size_t idx = ((size_t)b * SPATIAL + s0 + s) * 128 + c;
        g_xt_hi[idx] = hi;
        g_xt_lo[idx] = __float2bfloat16(vlo);
    }
}

// ---------------------------------------------------------------------------
// P2: Hamilton-product block expansion.
// ---------------------------------------------------------------------------
__global__ void expand_hamilton(const float* __restrict__ r,
                                const float* __restrict__ i_,
                                const float* __restrict__ j_,
                                const float* __restrict__ k_,
                                int dest, int O4, int C4, int T) {
    int idx = blockIdx.x * blockDim.x + threadIdx.x;
    int total = 16 * O4 * C4 * T;
    if (idx >= total) return;

    int tap = idx % T;
    int rem = idx / T;
    int C = 4 * C4;
    int c = rem % C;
    int o = rem / C;
    int br = o / O4, oo = o % O4;
    int bc = c / C4, cc = c % C4;

    const int   src[16] = {0,1,2,3, 1,0,3,2, 2,3,0,1, 3,2,1,0};
    const float sgn[16] = {1.f,-1.f,-1.f,-1.f, 1.f,1.f,-1.f,1.f,
                           1.f,1.f,1.f,-1.f,  1.f,-1.f,1.f,1.f};
    const float* comp[4] = {r, i_, j_, k_};

    float v = sgn[br * 4 + bc] * comp[src[br * 4 + bc]][(oo * C4 + cc) * T + tap];
    if (dest == 0) g_Wqkv[idx] = v;
    else if (dest == 1) g_Wdw[idx] = v;
    else g_Wpo[idx] = v;
}

// ---------------------------------------------------------------------------
// P3: Weff per output row -> bf16 hi/lo at [o][tap*128+c]; tb fold.
// ---------------------------------------------------------------------------
__global__ __launch_bounds__(128)
void weff_o(const float* __restrict__ qkv_b) {
    int o = blockIdx.x;
    int c = threadIdx.x;

    __shared__ float wdw_s[288 + 8];
    __shared__ float wq_s[32 * 128];
    __shared__ float qb_s[384];

    for (int m = c; m < 384; m += 128) qb_s[m] = qkv_b[m];

    float acc[9], tbp[9];
#pragma unroll
    for (int t = 0; t < 9; ++t) { acc[t] = 0.f; tbp[t] = 0.f; }

    const float* wdw_row = g_Wdw + (size_t)o * 3456;

    for (int cb = 0; cb < 12; ++cb) {
        __syncthreads();
        for (int i = c; i < 288; i += 128)
            wdw_s[i] = wdw_row[cb * 288 + i];
        for (int i = c; i < 4096; i += 128) {
            int m = i >> 7, col = i & 127;
            wq_s[m * 128 + col] = g_Wqkv[(cb * 32 + m) * 128 + col];
        }
        __syncthreads();
#pragma unroll 4
        for (int m = 0; m < 32; ++m) {
            float wq = wq_s[m * 128 + c];
#pragma unroll
            for (int t = 0; t < 9; ++t)
                acc[t] = fmaf(wdw_s[m * 9 + t], wq, acc[t]);
        }
        if (c < 32) {
            float qb = qb_s[cb * 32 + c];
#pragma unroll
            for (int t = 0; t < 9; ++t)
                tbp[t] = fmaf(wdw_s[c * 9 + t], qb, tbp[t]);
        }
    }

#pragma unroll
    for (int t = 0; t < 9; ++t) {
        float a = acc[t];
        __nv_bfloat16 hi = __float2bfloat16(a);
        g_WeffHi[(size_t)o * 1152 + t * 128 + c] = hi;
        g_WeffLo[(size_t)o * 1152 + t * 128 + c] =
            __float2bfloat16(a - __bfloat162float(hi));
    }

    if (c < 32) {
#pragma unroll
        for (int t = 0; t < 9; ++t) {
            float v = tbp[t];
#pragma unroll
            for (int off = 16; off; off >>= 1)
                v += __shfl_xor_sync(0xffffffffu, v, off);
            if (c == 0) g_tb[o * 9 + t] = v;
        }
    }
}

// ---------------------------------------------------------------------------
// P4: conv via mma.sync, 2-stage cp.async pipeline.
// CTA = M128 x N256 (2 image rows). 8 warps 2(M)x4(N); warp tile 64x64.
// K: 9 taps x 2 chunks of 64 ch = 18 iterations x 4 k16-steps; hi/lo 3-pass.
// smem per stage: Ahi/Alo 16KB + Bhi/Blo 32KB = 96KB; 2 stages = 192KB.
// ---------------------------------------------------------------------------
#define ST_AHI 0
#define ST_ALO (16 * 1024)
#define ST_BHI (32 * 1024)
#define ST_BLO (64 * 1024)
#define STAGE_BYTES (96 * 1024)
#define CONV_SMEM (2 * STAGE_BYTES)

__device__ __forceinline__ void conv_fill(char* smem, uint32_t sbase, int tid,
                                          int it, int y0, int o0, int b) {
    int tap = it >> 1;
    int ch  = (it & 1) * 64;
    int dy = tap / 3 - 1, dx = tap % 3 - 1;
    uint32_t stg = sbase + (it & 1) * STAGE_BYTES;

    // A: [128 o][64 k] hi+lo = 2048 x 16B
    for (int i = tid; i < 2048; i += 256) {
        int half = i >> 10, row = (i >> 3) & 127, u = i & 7;
        const __nv_bfloat16* src =
            (half ? g_WeffLo : g_WeffHi) +
            (size_t)(o0 + row) * 1152 + tap * 128 + ch + u * 8;
        cp_async16(stg + (half ? ST_ALO : ST_AHI) + row * 128 +
                   ((u ^ (row & 7)) << 4), src, 16u);
    }
    // B: [256 n][64 k] hi+lo = 4096 x 16B, (dy,dx)-gathered, zero halo
    for (int i = tid; i < 4096; i += 256) {
        int half = i >> 11, n = (i >> 3) & 255, u = i & 7;
        int yy = y0 + (n >> 7) + dy;
        int xx = (n & 127) + dx;
        bool ok = ((unsigned)yy < 128u) && ((unsigned)xx < 128u);
        const __nv_bfloat16* src = ok
            ? (half ? g_xt_lo : g_xt_hi) +
              ((size_t)b * SPATIAL + yy * 128 + xx) * 128 + ch + u * 8
            : g_xt_hi;                       // dummy valid address
        cp_async16(stg + (half ? ST_BLO : ST_BHI) + n * 128 +
                   ((u ^ (n & 7)) << 4), src, ok ? 16u : 0u);
    }
    CP_COMMIT();
}

__global__ __launch_bounds__(256)
void conv_mma(const float* __restrict__ dwb) {
    extern __shared__ char smem[];
    uint32_t sbase = smem_to_u32(smem);
    int tid = threadIdx.x, wid = tid >> 5, lane = tid & 31;
    int y0 = blockIdx.x * 2;
    int o0 = blockIdx.y * 128;
    int b  = blockIdx.z;

    int warpM = wid >> 2;         // 0..1 -> 64 chans
    int warpN = wid & 3;          // 0..3 -> 64 pixels
    int lm = lane >> 3;
    int r8 = lane & 7;

    float acc[4][8][4];
#pragma unroll
    for (int mt = 0; mt < 4; ++mt)
#pragma unroll
        for (int nt = 0; nt < 8; ++nt)
#pragma unroll
            for (int q = 0; q < 4; ++q) acc[mt][nt][q] = 0.f;

    conv_fill(smem, sbase, tid, 0, y0, o0, b);
    conv_fill(smem, sbase, tid, 1, y0, o0, b);

    for (int it = 0; it < 18; ++it) {
        if (it < 16) CP_WAIT1(); else CP_WAIT0();
        __syncthreads();

        uint32_t stg = sbase + (it & 1) * STAGE_BYTES;
        uint32_t sAhi = stg + ST_AHI, sAlo = stg + ST_ALO;
        uint32_t sBhi = stg + ST_BHI, sBlo = stg + ST_BLO;

#pragma unroll
        for (int ks = 0; ks < 4; ++ks) {
            uint32_t bhi[16], blo[16];
#pragma unroll
            for (int p = 0; p < 4; ++p) {
                int rowB = warpN * 64 + p * 16 + ((lm >> 1) << 3) + r8;
                int unitB = ks * 2 + (lm & 1);
                ldsm4(&bhi[p * 4], sw_addr(sBhi, rowB, unitB));
                ldsm4(&blo[p * 4], sw_addr(sBlo, rowB, unitB));
            }
#pragma unroll
            for (int mt = 0; mt < 4; ++mt) {
                int rowA = warpM * 64 + mt * 16 + ((lm & 1) << 3) + r8;
                int unitA = ks * 2 + (lm >> 1);
                uint32_t ahi[4], alo[4];
                ldsm4(ahi, sw_addr(sAhi, rowA, unitA));
                ldsm4(alo, sw_addr(sAlo, rowA, unitA));
#pragma unroll
                for (int nt = 0; nt < 8; ++nt) {
                    mma_bf16(acc[mt][nt], ahi, &bhi[nt * 2]);
                    mma_bf16(acc[mt][nt], ahi, &blo[nt * 2]);
                    mma_bf16(acc[mt][nt], alo, &bhi[nt * 2]);
                }
            }
        }
        __syncthreads();
        if (it + 2 < 18)
            conv_fill(smem, sbase, tid, it + 2, y0, o0, b);
    }

    // bias triples for both rows into smem
    float* bias_s = (float*)smem;   // [2][128][3]
    if (tid < 256) {
        int r = tid >> 7, o_loc = tid & 127;
        int o = o0 + o_loc;
        int y = y0 + r;
        const float* t = &g_tb[o * 9];
        float f0 = (y >= 1) ? 1.f : 0.f;
        float f2 = (y <= 126) ? 1.f : 0.f;
        bias_s[tid * 3 + 0] = dwb[o] + f0 * t[1] + t[4] + f2 * t[7];
        bias_s[tid * 3 + 1] = f0 * t[0] + t[3] + f2 * t[6];
        bias_s[tid * 3 + 2] = f0 * t[2] + t[5] + f2 * t[8];
    }
    __syncthreads();

    // epilogue: warp covers row r = warpN>>1, x base (warpN&1)*64
    int r = warpN >> 1;
    int y = y0 + r;
    int xb = (warpN & 1) * 64;
    int rr = lane >> 2;
    int q2 = (lane & 3) * 2;
    bool doss = (o0 < 256);
#pragma unroll
    for (int mt = 0; mt < 4; ++mt) {
#pragma unroll
        for (int half = 0; half < 2; ++half) {
            int o_loc = warpM * 64 + mt * 16 + rr + half * 8;
            int o = o0 + o_loc;
            int bi = (r * 128 + o_loc) * 3;
            float base = bias_s[bi + 0];
            float rs0  = bias_s[bi + 1];
            float rs2  = bias_s[bi + 2];
            float ss = 0.f;
            float* dst = g_qkv2 + (size_t)(b * 384 + o) * SPATIAL + y * 128;
#pragma unroll
            for (int nt = 0; nt < 8; ++nt) {
                int x = xb + nt * 8 + q2;
                float v0 = acc[mt][nt][half * 2 + 0] + base + rs2;
                if (x >= 1) v0 += rs0;
                float v1 = acc[mt][nt][half * 2 + 1] + base + rs0;
                if (x + 1 <= 126) v1 += rs2;
                *(float2*)(dst + x) = make_float2(v0, v1);
                ss = fmaf(v0, v0, ss);
                ss = fmaf(v1, v1, ss);
            }
            ss += __shfl_xor_sync(0xffffffffu, ss, 1);
            ss += __shfl_xor_sync(0xffffffffu, ss, 2);
            if (doss && (lane & 3) == 0)
                atomicAdd(&g_ss[b * 256 + o], ss);
        }
    }
}

// ---------------------------------------------------------------------------
// P5: finish inverse norms.
// ---------------------------------------------------------------------------
__global__ void norms_finish() {
    int r = blockIdx.x * 256 + threadIdx.x;
    if (r >= 512) return;
    int qk = r >> 8;
    int b  = (r >> 7) & 1;
    int ch = r & 127;
    float ss = g_ss[b * 256 + qk * 128 + ch];
    g_inv[r] = 1.f / fmaxf(sqrtf(ss), 1e-12f);
}

// ---------------------------------------------------------------------------
// P6: attn partial sums (32 K-slices x 8 bh, atomics).
// ---------------------------------------------------------------------------
__global__ void attn_partial() {
    int slice = blockIdx.x;
    int bh = blockIdx.y;
    int b = bh >> 2, h = bh & 3;
    const float* qb = g_qkv2 + (size_t)(b * 384 + h * 32) * SPATIAL;
    const float* kb = g_qkv2 + (size_t)(b * 384 + 128 + h * 32) * SPATIAL;

    __shared__ float qs[32][65], ks[32][65];
    int tid = threadIdx.x;
    int c = tid >> 3;
    int d0 = (tid & 7) * 4;
    float acc[4] = {0.f, 0.f, 0.f, 0.f};

    for (int sub = 0; sub < 8; ++sub) {
        int s0 = slice * 512 + sub * 64;
        for (int i = tid; i < 2048; i += 256) {
            int cc = i >> 6, kk = i & 63;
            qs[cc][kk] = qb[(size_t)cc * SPATIAL + s0 + kk];
            ks[cc][kk] = kb[(size_t)cc * SPATIAL + s0 + kk];
        }
        __syncthreads();
#pragma unroll 8
        for (int kk = 0; kk < 64; ++kk) {
            float qv = qs[c][kk];
#pragma unroll
            for (int j = 0; j < 4; ++j)
                acc[j] = fmaf(qv, ks[d0 + j][kk], acc[j]);
        }
        __syncthreads();
    }
#pragma unroll
    for (int j = 0; j < 4; ++j)
        atomicAdd(&g_attnP[(bh * 32 + c) * 32 + d0 + j], acc[j]);
}

// ---------------------------------------------------------------------------
// P7: softmax with inv-norms and temperature fused in.
// ---------------------------------------------------------------------------
__global__ void softmax_kernel(const float* __restrict__ temp) {
    int row = blockIdx.x;
    int bh = row >> 5, c = row & 31;
    int b = bh >> 2, h = bh & 3;
    int d = threadIdx.x;

    float invq = g_inv[b * 128 + h * 32 + c];
    float invk = g_inv[256 + b * 128 + h * 32 + d];
    float v = g_attnP[row * 32 + d] * invq * invk * temp[h];

    float mx = v;
#pragma unroll
    for (int off = 16; off; off >>= 1)
        mx = fmaxf(mx, __shfl_xor_sync(0xffffffffu, mx, off));
    float e = expf(v - mx);
    float s = e;
#pragma unroll
    for (int off = 16; off; off >>= 1)
        s += __shfl_xor_sync(0xffffffffu, s, off);
    g_attn[row * 32 + d] = e / s;
}

// ---------------------------------------------------------------------------
// P8: M2[b][o][h*32+d] = sum_c Wpo[o][h*32+c] * attn[bh][c][d]
// ---------------------------------------------------------------------------
__global__ void make_M2() {
    int b = blockIdx.x, h = blockIdx.y;
    int bh = b * 4 + h;
    int tid = threadIdx.x;

    __shared__ float A[32][33];
    __shared__ float W[128][33];

    for (int i = tid; i < 1024; i += 256) {
        int c = i >> 5, d = i & 31;
        A[c][d] = g_attn[(bh * 32 + c) * 32 + d];
    }
    for (int i = tid; i < 4096; i += 256) {
        int o = i >> 5, c = i & 31;
        W[o][c] = g_Wpo[o * 128 + h * 32 + c];
    }
    __syncthreads();

    int o = tid >> 1;
    int d0 = (tid & 1) * 16;
#pragma unroll
    for (int dd = 0; dd < 16; ++dd) {
        int d = d0 + dd;
        float s = 0.f;
#pragma unroll
        for (int c = 0; c < 32; ++c)
            s = fmaf(W[o][c], A[c][d], s);
        g_M2[b * 16384 + o * 128 + h * 32 + d] = s;
    }
}

// ---------------------------------------------------------------------------
// P9: out[b][o][s] = sum_dg M2[b][o][dg] * v[b][dg][s] + po_b[o]  (fp32x2)
// ---------------------------------------------------------------------------
__global__ __launch_bounds__(256)
void final_gemm(const float* __restrict__ pob, float* __restrict__ out) {
    int s0 = blockIdx.x * 128;
    int b  = blockIdx.z;
    int tid = threadIdx.x;
    int tr = tid >> 4, tc = tid & 15;

    __shared__ float As[16][128];
    __shared__ float Bs[16][132];

    u64 acc2[4][8];
#pragma unroll
    for (int mp = 0; mp < 4; ++mp)
#pragma unroll
        for (int n = 0; n < 8; ++n) acc2[mp][n] = 0ull;

    for (int cb = 0; cb < 8; ++cb) {
        for (int i = tid; i < 2048; i += 256) {
            int o = i >> 4, kk = i & 15;
            As[kk][o] = g_M2[b * 16384 + o * 128 + cb * 16 + kk];
        }
        for (int i = tid; i < 2048; i += 256) {
            int kk = i >> 7, sx = i & 127;
            Bs[kk][sx] = g_qkv2[(size_t)(b * 384 + 256 + cb * 16 + kk) * SPATIAL + s0 + sx];
        }
        __syncthreads();
#pragma unroll
        for (int kk = 0; kk < 16; ++kk) {
            u64 a2[4];
#pragma unroll
            for (int mp = 0; mp < 4; ++mp)
                a2[mp] = *(const u64*)&As[kk][tr * 8 + 2 * mp];
            const float* brow = &Bs[kk][tc * 8];
            float4 w0 = *(const float4*)brow;
            float4 w1 = *(const float4*)(brow + 4);
            u64 bb[8];
            bb[0] = pack2(w0.x, w0.x); bb[1] = pack2(w0.y, w0.y);
            bb[2] = pack2(w0.z, w0.z); bb[3] = pack2(w0.w, w0.w);
            bb[4] = pack2(w1.x, w1.x); bb[5] = pack2(w1.y, w1.y);
            bb[6] = pack2(w1.z, w1.z); bb[7] = pack2(w1.w, w1.w);
#pragma unroll
            for (int mp = 0; mp < 4; ++mp)
#pragma unroll
                for (int n = 0; n < 8; ++n)
                    acc2[mp][n] = fma2(a2[mp], bb[n], acc2[mp][n]);
        }
        __syncthreads();
    }

#pragma unroll
    for (int mp = 0; mp < 4; ++mp) {
        int oA = tr * 8 + 2 * mp;
        float b0 = pob[oA], b1 = pob[oA + 1];
        float* op0 = out + (size_t)(b * 128 + oA) * SPATIAL + s0 + tc * 8;
        float* op1 = op0 + SPATIAL;
#pragma unroll
        for (int n = 0; n < 8; ++n) {
            float2 v = unpack2(acc2[mp][n]);
            op0[n] = v.x + b0;
            op1[n] = v.y + b1;
        }
    }
}

// ---------------------------------------------------------------------------
extern "C" void kernel_launch(void* const* d_in, const int* in_sizes, int n_in,
                              void* d_out, int out_size) {
    const float* x     = (const float*)d_in[0];
    const float* qkv_r = (const float*)d_in[1];
    const float* qkv_i = (const float*)d_in[2];
    const float* qkv_j = (const float*)d_in[3];
    const float* qkv_k = (const float*)d_in[4];
    const float* qkv_b = (const float*)d_in[5];
    const float* dw_r  = (const float*)d_in[6];
    const float* dw_i  = (const float*)d_in[7];
    const float* dw_j  = (const float*)d_in[8];
    const float* dw_k  = (const float*)d_in[9];
    const float* dw_b  = (const float*)d_in[10];
    const float* po_r  = (const float*)d_in[11];
    const float* po_i  = (const float*)d_in[12];
    const float* po_j  = (const float*)d_in[13];
    const float* po_k  = (const float*)d_in[14];
    const float* po_b  = (const float*)d_in[15];
    const float* temp  = (const float*)d_in[16];
    float* out = (float*)d_out;

    cudaFuncSetAttribute(conv_mma, cudaFuncAttributeMaxDynamicSharedMemorySize,
                         CONV_SMEM);

    // launches 1..5 (conv is the 6th for ncu -s 5 -c 1)
    prep_x<<<dim3(512, 2), 256>>>(x);
    expand_hamilton<<<192, 256>>>(qkv_r, qkv_i, qkv_j, qkv_k, 0, 96, 32, 1);
    expand_hamilton<<<5184, 256>>>(dw_r, dw_i, dw_j, dw_k, 1, 96, 96, 9);
    expand_hamilton<<<64, 256>>>(po_r, po_i, po_j, po_k, 2, 32, 32, 1);
    weff_o<<<384, 128>>>(qkv_b);

    // launch 6: pipelined HMMA conv
    conv_mma<<<dim3(64, 3, 2), 256, CONV_SMEM>>>(dw_b);

    // attention tail
    norms_finish<<<2, 256>>>();
    attn_partial<<<dim3(32, 8), 256>>>();
    softmax_kernel<<<256, 32>>>(temp);
    make_M2<<<dim3(2, 4), 256>>>();
    final_gemm<<<dim3(128, 1, 2), 256>>>(po_b, out);
}

// round 7
// speedup vs baseline: 1.6263x; 1.6263x over previous
#include <cuda_runtime.h>
#include <cuda_bf16.h>
#include <cstdint>
#include <math.h>

// ---------------------------------------------------------------------------
// QAttention round 7: HMMA conv, round-5 geometry (N=128, 2+ CTAs/SM) plus
// cp.async double-buffering with 32KB stages (K-chunk 32, 36 iterations).
// ---------------------------------------------------------------------------

#define SPATIAL 16384
typedef unsigned long long u64;

// ------------------------- mma.sync helpers --------------------------------
__device__ __forceinline__ uint32_t smem_to_u32(const void* p) {
    uint32_t a;
    asm("{ .reg .u64 t; cvta.to.shared.u64 t, %1; cvt.u32.u64 %0, t; }"
        : "=r"(a) : "l"(p));
    return a;
}
__device__ __forceinline__ void ldsm4(uint32_t* r, uint32_t addr) {
    asm volatile("ldmatrix.sync.aligned.m8n8.x4.shared.b16 {%0,%1,%2,%3}, [%4];"
                 : "=r"(r[0]), "=r"(r[1]), "=r"(r[2]), "=r"(r[3]) : "r"(addr));
}
__device__ __forceinline__ void mma_bf16(float* d, const uint32_t* a,
                                         const uint32_t* b) {
    asm volatile(
        "mma.sync.aligned.m16n8k16.row.col.f32.bf16.bf16.f32 "
        "{%0,%1,%2,%3}, {%4,%5,%6,%7}, {%8,%9}, {%0,%1,%2,%3};"
        : "+f"(d[0]), "+f"(d[1]), "+f"(d[2]), "+f"(d[3])
        : "r"(a[0]), "r"(a[1]), "r"(a[2]), "r"(a[3]), "r"(b[0]), "r"(b[1]));
}
// 64B-row swizzle: 4 units of 16B per row; unit ^= (row>>1)&3 keeps all 8
// ldmatrix rows in distinct 16B offsets mod 128 (conflict-free).
__device__ __forceinline__ uint32_t sw64(uint32_t base, int row, int unit) {
    return base + row * 64 + (((unit ^ ((row >> 1) & 3)) & 3) << 4);
}
__device__ __forceinline__ void cp_async16(uint32_t saddr, const void* gptr,
                                           uint32_t bytes) {
    asm volatile("cp.async.cg.shared.global [%0], [%1], 16, %2;"
                 :: "r"(saddr), "l"(gptr), "r"(bytes) : "memory");
}
#define CP_COMMIT() asm volatile("cp.async.commit_group;" ::: "memory")
#define CP_WAIT1()  asm volatile("cp.async.wait_group 1;" ::: "memory")
#define CP_WAIT0()  asm volatile("cp.async.wait_group 0;" ::: "memory")

// ------------------------- f32x2 helpers (final_gemm) ----------------------
__device__ __forceinline__ u64 pack2(float lo, float hi) {
    u64 r; asm("mov.b64 %0,{%1,%2};" : "=l"(r) : "f"(lo), "f"(hi)); return r;
}
__device__ __forceinline__ float2 unpack2(u64 v) {
    float2 f; asm("mov.b64 {%0,%1},%2;" : "=f"(f.x), "=f"(f.y) : "l"(v)); return f;
}
__device__ __forceinline__ u64 fma2(u64 a, u64 b, u64 c) {
    u64 d; asm("fma.rn.f32x2 %0,%1,%2,%3;" : "=l"(d) : "l"(a), "l"(b), "l"(c)); return d;
}

// ------------------------- device scratch ----------------------------------
__device__ float g_Wqkv[384 * 128];
__device__ float g_Wdw[384 * 384 * 9];
__device__ float g_Wpo[128 * 128];
__device__ __nv_bfloat16 g_WeffHi[384 * 1152];   // [o][tap*128+c]
__device__ __nv_bfloat16 g_WeffLo[384 * 1152];
__device__ float g_tb[384 * 9];
__device__ __nv_bfloat16 g_xt_hi[2 * SPATIAL * 128];  // [b][s][c]
__device__ __nv_bfloat16 g_xt_lo[2 * SPATIAL * 128];
__device__ float g_qkv2[2 * 384 * SPATIAL];
__device__ float g_attnP[2 * 4 * 32 * 32];
__device__ float g_attn[2 * 4 * 32 * 32];
__device__ float g_inv[2 * 2 * 128];
__device__ float g_ss[2 * 256];
__device__ float g_M2[2 * 128 * 128];

// ---------------------------------------------------------------------------
// P1: transpose x to [b][s][c] bf16 hi/lo; block(0,0) also zeros scratch.
// ---------------------------------------------------------------------------
__global__ void prep_x(const float* __restrict__ X) {
    __shared__ float t[128][33];
    int s0 = blockIdx.x * 32;
    int b  = blockIdx.y;
    int tid = threadIdx.x;

    if (blockIdx.x == 0 && b == 0) {
        for (int i = tid; i < 8192; i += 256) g_attnP[i] = 0.f;
        for (int i = tid; i < 512; i += 256) g_ss[i] = 0.f;
    }
    for (int i = tid; i < 4096; i += 256) {
        int c = i >> 5, s = i & 31;
        t[c][s] = X[((size_t)(b * 128 + c)) * SPATIAL + s0 + s];
    }
    __syncthreads();
    for (int i = tid; i < 4096; i += 256) {
        int s = i >> 7, c = i & 127;
        float v = t[c][s];
        __nv_bfloat16 hi = __float2bfloat16(v);
        float vlo = v - __bfloat162float(hi);
        size_t idx = ((size_t)b * SPATIAL + s0 + s) * 128 + c;
        g_xt_hi[idx] = hi;
        g_xt_lo[idx] = __float2bfloat16(vlo);
    }
}

// ---------------------------------------------------------------------------
// P2: Hamilton-product block expansion.
// ---------------------------------------------------------------------------
__global__ void expand_hamilton(const float* __restrict__ r,
                                const float* __restrict__ i_,
                                const float* __restrict__ j_,
                                const float* __restrict__ k_,
                                int dest, int O4, int C4, int T) {
    int idx = blockIdx.x * blockDim.x + threadIdx.x;
    int total = 16 * O4 * C4 * T;
    if (idx >= total) return;

    int tap = idx % T;
    int rem = idx / T;
    int C = 4 * C4;
    int c = rem % C;
    int o = rem / C;
    int br = o / O4, oo = o % O4;
    int bc = c / C4, cc = c % C4;

    const int   src[16] = {0,1,2,3, 1,0,3,2, 2,3,0,1, 3,2,1,0};
    const float sgn[16] = {1.f,-1.f,-1.f,-1.f, 1.f,1.f,-1.f,1.f,
                           1.f,1.f,1.f,-1.f,  1.f,-1.f,1.f,1.f};
    const float* comp[4] = {r, i_, j_, k_};

    float v = sgn[br * 4 + bc] * comp[src[br * 4 + bc]][(oo * C4 + cc) * T + tap];
    if (dest == 0) g_Wqkv[idx] = v;
    else if (dest == 1) g_Wdw[idx] = v;
    else g_Wpo[idx] = v;
}

// ---------------------------------------------------------------------------
// P3: Weff per output row -> bf16 hi/lo at [o][tap*128+c]; tb fold.
// ---------------------------------------------------------------------------
__global__ __launch_bounds__(128)
void weff_o(const float* __restrict__ qkv_b) {
    int o = blockIdx.x;
    int c = threadIdx.x;

    __shared__ float wdw_s[288 + 8];
    __shared__ float wq_s[32 * 128];
    __shared__ float qb_s[384];

    for (int m = c; m < 384; m += 128) qb_s[m] = qkv_b[m];

    float acc[9], tbp[9];
#pragma unroll
    for (int t = 0; t < 9; ++t) { acc[t] = 0.f; tbp[t] = 0.f; }

    const float* wdw_row = g_Wdw + (size_t)o * 3456;

    for (int cb = 0; cb < 12; ++cb) {
        __syncthreads();
        for (int i = c; i < 288; i += 128)
            wdw_s[i] = wdw_row[cb * 288 + i];
        for (int i = c; i < 4096; i += 128) {
            int m = i >> 7, col = i & 127;
            wq_s[m * 128 + col] = g_Wqkv[(cb * 32 + m) * 128 + col];
        }
        __syncthreads();
#pragma unroll 4
        for (int m = 0; m < 32; ++m) {
            float wq = wq_s[m * 128 + c];
#pragma unroll
            for (int t = 0; t < 9; ++t)
                acc[t] = fmaf(wdw_s[m * 9 + t], wq, acc[t]);
        }
        if (c < 32) {
            float qb = qb_s[cb * 32 + c];
#pragma unroll
            for (int t = 0; t < 9; ++t)
                tbp[t] = fmaf(wdw_s[c * 9 + t], qb, tbp[t]);
        }
    }

#pragma unroll
    for (int t = 0; t < 9; ++t) {
        float a = acc[t];
        __nv_bfloat16 hi = __float2bfloat16(a);
        g_WeffHi[(size_t)o * 1152 + t * 128 + c] = hi;
        g_WeffLo[(size_t)o * 1152 + t * 128 + c] =
            __float2bfloat16(a - __bfloat162float(hi));
    }

    if (c < 32) {
#pragma unroll
        for (int t = 0; t < 9; ++t) {
            float v = tbp[t];
#pragma unroll
            for (int off = 16; off; off >>= 1)
                v += __shfl_xor_sync(0xffffffffu, v, off);
            if (c == 0) g_tb[o * 9 + t] = v;
        }
    }
}

// ---------------------------------------------------------------------------
// P4: conv via mma.sync, 2-stage cp.async pipeline, 32KB stages.
// CTA = M128 x N128 (one image row y). 8 warps 2(M)x4(N); warp tile 64x32.
// K: 9 taps x 4 chunks of 32 ch = 36 iterations x 2 k16-steps; hi/lo 3-pass.
// Stage: Ahi/Alo 8KB each + Bhi/Blo 8KB each = 32KB; 2 stages = 64KB.
// ---------------------------------------------------------------------------
#define ST_AHI 0
#define ST_ALO (8 * 1024)
#define ST_BHI (16 * 1024)
#define ST_BLO (24 * 1024)
#define STAGE_BYTES (32 * 1024)
#define CONV_SMEM (2 * STAGE_BYTES)

__device__ __forceinline__ void conv_fill(uint32_t sbase, int tid,
                                          int it, int y, int o0, int b) {
    int tap = it >> 2;
    int ch  = (it & 3) * 32;
    int dy = tap / 3 - 1, dx = tap % 3 - 1;
    uint32_t stg = sbase + (it & 1) * STAGE_BYTES;

    // A: [128 o][32 k] hi+lo = 1024 x 16B
    for (int i = tid; i < 1024; i += 256) {
        int half = i >> 9, rem = i & 511, row = rem >> 2, u = rem & 3;
        const __nv_bfloat16* src =
            (half ? g_WeffLo : g_WeffHi) +
            (size_t)(o0 + row) * 1152 + tap * 128 + ch + u * 8;
        cp_async16(sw64(stg + (half ? ST_ALO : ST_AHI), row, u), src, 16u);
    }
    // B: [128 n][32 k] hi+lo = 1024 x 16B, (dy,dx)-gathered, zero halo
    int yy = y + dy;
    bool yok = (unsigned)yy < 128u;
    for (int i = tid; i < 1024; i += 256) {
        int half = i >> 9, rem = i & 511, n = rem >> 2, u = rem & 3;
        int xx = n + dx;
        bool ok = yok && ((unsigned)xx < 128u);
        const __nv_bfloat16* src = ok
            ? (half ? g_xt_lo : g_xt_hi) +
              ((size_t)b * SPATIAL + yy * 128 + xx) * 128 + ch + u * 8
            : g_xt_hi;
        cp_async16(sw64(stg + (half ? ST_BLO : ST_BHI), n, u), src,
                   ok ? 16u : 0u);
    }
    CP_COMMIT();
}

__global__ __launch_bounds__(256)
void conv_mma(const float* __restrict__ dwb) {
    extern __shared__ char smem[];
    uint32_t sbase = smem_to_u32(smem);
    int tid = threadIdx.x, wid = tid >> 5, lane = tid & 31;
    int y  = blockIdx.x;          // image row
    int o0 = blockIdx.y * 128;    // output-channel tile
    int b  = blockIdx.z;

    int warpM = wid >> 2;         // 0..1 -> 64 chans
    int warpN = wid & 3;          // 0..3 -> 32 pixels
    int lm = lane >> 3;
    int r8 = lane & 7;

    float acc[4][4][4];
#pragma unroll
    for (int mt = 0; mt < 4; ++mt)
#pragma unroll
        for (int nt = 0; nt < 4; ++nt)
#pragma unroll
            for (int q = 0; q < 4; ++q) acc[mt][nt][q] = 0.f;

    conv_fill(sbase, tid, 0, y, o0, b);
    conv_fill(sbase, tid, 1, y, o0, b);

    for (int it = 0; it < 36; ++it) {
        if (it < 34) CP_WAIT1(); else CP_WAIT0();
        __syncthreads();

        uint32_t stg = sbase + (it & 1) * STAGE_BYTES;
        uint32_t sAhi = stg + ST_AHI, sAlo = stg + ST_ALO;
        uint32_t sBhi = stg + ST_BHI, sBlo = stg + ST_BLO;

#pragma unroll
        for (int ks = 0; ks < 2; ++ks) {
            uint32_t bhi[8], blo[8];
#pragma unroll
            for (int p = 0; p < 2; ++p) {
                int rowB = warpN * 32 + p * 16 + ((lm >> 1) << 3) + r8;
                int unitB = ks * 2 + (lm & 1);
                ldsm4(&bhi[p * 4], sw64(sBhi, rowB, unitB));
                ldsm4(&blo[p * 4], sw64(sBlo, rowB, unitB));
            }
#pragma unroll
            for (int mt = 0; mt < 4; ++mt) {
                int rowA = warpM * 64 + mt * 16 + ((lm & 1) << 3) + r8;
                int unitA = ks * 2 + (lm >> 1);
                uint32_t ahi[4], alo[4];
                ldsm4(ahi, sw64(sAhi, rowA, unitA));
                ldsm4(alo, sw64(sAlo, rowA, unitA));
#pragma unroll
                for (int nt = 0; nt < 4; ++nt) {
                    mma_bf16(acc[mt][nt], ahi, &bhi[nt * 2]);
                    mma_bf16(acc[mt][nt], ahi, &blo[nt * 2]);
                    mma_bf16(acc[mt][nt], alo, &bhi[nt * 2]);
                }
            }
        }
        __syncthreads();
        if (it + 2 < 36)
            conv_fill(sbase, tid, it + 2, y, o0, b);
    }

    // bias triple per local o into smem
    float* bias_s = (float*)smem;   // [128][3]
    if (tid < 128) {
        int o = o0 + tid;
        const float* t = &g_tb[o * 9];
        float f0 = (y >= 1) ? 1.f : 0.f;
        float f2 = (y <= 126) ? 1.f : 0.f;
        bias_s[tid * 3 + 0] = dwb[o] + f0 * t[1] + t[4] + f2 * t[7];
        bias_s[tid * 3 + 1] = f0 * t[0] + t[3] + f2 * t[6];
        bias_s[tid * 3 + 2] = f0 * t[2] + t[5] + f2 * t[8];
    }
    __syncthreads();

    int rr = lane >> 2;
    int q2 = (lane & 3) * 2;
    bool doss = (o0 < 256);
#pragma unroll
    for (int mt = 0; mt < 4; ++mt) {
#pragma unroll
        for (int half = 0; half < 2; ++half) {
            int o_loc = warpM * 64 + mt * 16 + rr + half * 8;
            int o = o0 + o_loc;
            float base = bias_s[o_loc * 3 + 0];
            float rs0  = bias_s[o_loc * 3 + 1];
            float rs2  = bias_s[o_loc * 3 + 2];
            float ss = 0.f;
            float* dst = g_qkv2 + (size_t)(b * 384 + o) * SPATIAL + y * 128;
#pragma unroll
            for (int nt = 0; nt < 4; ++nt) {
                int x = warpN * 32 + nt * 8 + q2;
                float v0 = acc[mt][nt][half * 2 + 0] + base + rs2;
                if (x >= 1) v0 += rs0;
                float v1 = acc[mt][nt][half * 2 + 1] + base + rs0;
                if (x + 1 <= 126) v1 += rs2;
                *(float2*)(dst + x) = make_float2(v0, v1);
                ss = fmaf(v0, v0, ss);
                ss = fmaf(v1, v1, ss);
            }
            ss += __shfl_xor_sync(0xffffffffu, ss, 1);
            ss += __shfl_xor_sync(0xffffffffu, ss, 2);
            if (doss && (lane & 3) == 0)
                atomicAdd(&g_ss[b * 256 + o], ss);
        }
    }
}

// ---------------------------------------------------------------------------
// P5: finish inverse norms.
// ---------------------------------------------------------------------------
__global__ void norms_finish() {
    int r = blockIdx.x * 256 + threadIdx.x;
    if (r >= 512) return;
    int qk = r >> 8;
    int b  = (r >> 7) & 1;
    int ch = r & 127;
    float ss = g_ss[b * 256 + qk * 128 + ch];
    g_inv[r] = 1.f / fmaxf(sqrtf(ss), 1e-12f);
}

// ---------------------------------------------------------------------------
// P6: attn partial sums (32 K-slices x 8 bh, atomics).
// ---------------------------------------------------------------------------
__global__ void attn_partial() {
    int slice = blockIdx.x;
    int bh = blockIdx.y;
    int b = bh >> 2, h = bh & 3;
    const float* qb = g_qkv2 + (size_t)(b * 384 + h * 32) * SPATIAL;
    const float* kb = g_qkv2 + (size_t)(b * 384 + 128 + h * 32) * SPATIAL;

    __shared__ float qs[32][65], ks[32][65];
    int tid = threadIdx.x;
    int c = tid >> 3;
    int d0 = (tid & 7) * 4;
    float acc[4] = {0.f, 0.f, 0.f, 0.f};

    for (int sub = 0; sub < 8; ++sub) {
        int s0 = slice * 512 + sub * 64;
        for (int i = tid; i < 2048; i += 256) {
            int cc = i >> 6, kk = i & 63;
            qs[cc][kk] = qb[(size_t)cc * SPATIAL + s0 + kk];
            ks[cc][kk] = kb[(size_t)cc * SPATIAL + s0 + kk];
        }
        __syncthreads();
#pragma unroll 8
        for (int kk = 0; kk < 64; ++kk) {
            float qv = qs[c][kk];
#pragma unroll
            for (int j = 0; j < 4; ++j)
                acc[j] = fmaf(qv, ks[d0 + j][kk], acc[j]);
        }
        __syncthreads();
    }
#pragma unroll
    for (int j = 0; j < 4; ++j)
        atomicAdd(&g_attnP[(bh * 32 + c) * 32 + d0 + j], acc[j]);
}

// ---------------------------------------------------------------------------
// P7: softmax with inv-norms and temperature fused in.
// ---------------------------------------------------------------------------
__global__ void softmax_kernel(const float* __restrict__ temp) {
    int row = blockIdx.x;
    int bh = row >> 5, c = row & 31;
    int b = bh >> 2, h = bh & 3;
    int d = threadIdx.x;

    float invq = g_inv[b * 128 + h * 32 + c];
    float invk = g_inv[256 + b * 128 + h * 32 + d];
    float v = g_attnP[row * 32 + d] * invq * invk * temp[h];

    float mx = v;
#pragma unroll
    for (int off = 16; off; off >>= 1)
        mx = fmaxf(mx, __shfl_xor_sync(0xffffffffu, mx, off));
    float e = expf(v - mx);
    float s = e;
#pragma unroll
    for (int off = 16; off; off >>= 1)
        s += __shfl_xor_sync(0xffffffffu, s, off);
    g_attn[row * 32 + d] = e / s;
}

// ---------------------------------------------------------------------------
// P8: M2[b][o][h*32+d] = sum_c Wpo[o][h*32+c] * attn[bh][c][d]
// ---------------------------------------------------------------------------
__global__ void make_M2() {
    int b = blockIdx.x, h = blockIdx.y;
    int bh = b * 4 + h;
    int tid = threadIdx.x;

    __shared__ float A[32][33];
    __shared__ float W[128][33];

    for (int i = tid; i < 1024; i += 256) {
        int c = i >> 5, d = i & 31;
        A[c][d] = g_attn[(bh * 32 + c) * 32 + d];
    }
    for (int i = tid; i < 4096; i += 256) {
        int o = i >> 5, c = i & 31;
        W[o][c] = g_Wpo[o * 128 + h * 32 + c];
    }
    __syncthreads();

    int o = tid >> 1;
    int d0 = (tid & 1) * 16;
#pragma unroll
    for (int dd = 0; dd < 16; ++dd) {
        int d = d0 + dd;
        float s = 0.f;
#pragma unroll
        for (int c = 0; c < 32; ++c)
            s = fmaf(W[o][c], A[c][d], s);
        g_M2[b * 16384 + o * 128 + h * 32 + d] = s;
    }
}

// ---------------------------------------------------------------------------
// P9: out[b][o][s] = sum_dg M2[b][o][dg] * v[b][dg][s] + po_b[o]  (fp32x2)
// ---------------------------------------------------------------------------
__global__ __launch_bounds__(256)
void final_gemm(const float* __restrict__ pob, float* __restrict__ out) {
    int s0 = blockIdx.x * 128;
    int b  = blockIdx.z;
    int tid = threadIdx.x;
    int tr = tid >> 4, tc = tid & 15;

    __shared__ float As[16][128];
    __shared__ float Bs[16][132];

    u64 acc2[4][8];
#pragma unroll
    for (int mp = 0; mp < 4; ++mp)
#pragma unroll
        for (int n = 0; n < 8; ++n) acc2[mp][n] = 0ull;

    for (int cb = 0; cb < 8; ++cb) {
        for (int i = tid; i < 2048; i += 256) {
            int o = i >> 4, kk = i & 15;
            As[kk][o] = g_M2[b * 16384 + o * 128 + cb * 16 + kk];
        }
        for (int i = tid; i < 2048; i += 256) {
            int kk = i >> 7, sx = i & 127;
            Bs[kk][sx] = g_qkv2[(size_t)(b * 384 + 256 + cb * 16 + kk) * SPATIAL + s0 + sx];
        }
        __syncthreads();
#pragma unroll
        for (int kk = 0; kk < 16; ++kk) {
            u64 a2[4];
#pragma unroll
            for (int mp = 0; mp < 4; ++mp)
                a2[mp] = *(const u64*)&As[kk][tr * 8 + 2 * mp];
            const float* brow = &Bs[kk][tc * 8];
            float4 w0 = *(const float4*)brow;
            float4 w1 = *(const float4*)(brow + 4);
            u64 bb[8];
            bb[0] = pack2(w0.x, w0.x); bb[1] = pack2(w0.y, w0.y);
            bb[2] = pack2(w0.z, w0.z); bb[3] = pack2(w0.w, w0.w);
            bb[4] = pack2(w1.x, w1.x); bb[5] = pack2(w1.y, w1.y);
            bb[6] = pack2(w1.z, w1.z); bb[7] = pack2(w1.w, w1.w);
#pragma unroll
            for (int mp = 0; mp < 4; ++mp)
#pragma unroll
                for (int n = 0; n < 8; ++n)
                    acc2[mp][n] = fma2(a2[mp], bb[n], acc2[mp][n]);
        }
        __syncthreads();
    }

#pragma unroll
    for (int mp = 0; mp < 4; ++mp) {
        int oA = tr * 8 + 2 * mp;
        float b0 = pob[oA], b1 = pob[oA + 1];
        float* op0 = out + (size_t)(b * 128 + oA) * SPATIAL + s0 + tc * 8;
        float* op1 = op0 + SPATIAL;
#pragma unroll
        for (int n = 0; n < 8; ++n) {
            float2 v = unpack2(acc2[mp][n]);
            op0[n] = v.x + b0;
            op1[n] = v.y + b1;
        }
    }
}

// ---------------------------------------------------------------------------
extern "C" void kernel_launch(void* const* d_in, const int* in_sizes, int n_in,
                              void* d_out, int out_size) {
    const float* x     = (const float*)d_in[0];
    const float* qkv_r = (const float*)d_in[1];
    const float* qkv_i = (const float*)d_in[2];
    const float* qkv_j = (const float*)d_in[3];
    const float* qkv_k = (const float*)d_in[4];
    const float* qkv_b = (const float*)d_in[5];
    const float* dw_r  = (const float*)d_in[6];
    const float* dw_i  = (const float*)d_in[7];
    const float* dw_j  = (const float*)d_in[8];
    const float* dw_k  = (const float*)d_in[9];
    const float* dw_b  = (const float*)d_in[10];
    const float* po_r  = (const float*)d_in[11];
    const float* po_i  = (const float*)d_in[12];
    const float* po_j  = (const float*)d_in[13];
    const float* po_k  = (const float*)d_in[14];
    const float* po_b  = (const float*)d_in[15];
    const float* temp  = (const float*)d_in[16];
    float* out = (float*)d_out;

    cudaFuncSetAttribute(conv_mma, cudaFuncAttributeMaxDynamicSharedMemorySize,
                         CONV_SMEM);

    // launches 1..5 (conv is the 6th for ncu -s 5 -c 1)
    prep_x<<<dim3(512, 2), 256>>>(x);
    expand_hamilton<<<192, 256>>>(qkv_r, qkv_i, qkv_j, qkv_k, 0, 96, 32, 1);
    expand_hamilton<<<5184, 256>>>(dw_r, dw_i, dw_j, dw_k, 1, 96, 96, 9);
    expand_hamilton<<<64, 256>>>(po_r, po_i, po_j, po_k, 2, 32, 32, 1);
    weff_o<<<384, 128>>>(qkv_b);

    // launch 6: pipelined HMMA conv (N=128 geometry, 2+ CTAs/SM)
    conv_mma<<<dim3(128, 3, 2), 256, CONV_SMEM>>>(dw_b);

    // attention tail
    norms_finish<<<2, 256>>>();
    attn_partial<<<dim3(32, 8), 256>>>();
    softmax_kernel<<<256, 32>>>(temp);
    make_M2<<<dim3(2, 4), 256>>>();
    final_gemm<<<dim3(128, 1, 2), 256>>>(po_b, out);
}

// round 8
// speedup vs baseline: 2.5382x; 1.5607x over previous
#include <cuda_runtime.h>
#include <cuda_fp16.h>
#include <cstdint>
#include <math.h>

// ---------------------------------------------------------------------------
// QAttention round 8: conv via single-pass fp16 mma.sync (3x fewer HMMA than
// the bf16 hi/lo 3-pass). Round-5 geometry (validated fragment maps), cp.async
// double-buffer, 32KB stages, 2 CTAs/SM.
// ---------------------------------------------------------------------------

#define SPATIAL 16384
typedef unsigned long long u64;

// ------------------------- mma.sync helpers --------------------------------
__device__ __forceinline__ uint32_t smem_to_u32(const void* p) {
    uint32_t a;
    asm("{ .reg .u64 t; cvta.to.shared.u64 t, %1; cvt.u32.u64 %0, t; }"
        : "=r"(a) : "l"(p));
    return a;
}
__device__ __forceinline__ void ldsm4(uint32_t* r, uint32_t addr) {
    asm volatile("ldmatrix.sync.aligned.m8n8.x4.shared.b16 {%0,%1,%2,%3}, [%4];"
                 : "=r"(r[0]), "=r"(r[1]), "=r"(r[2]), "=r"(r[3]) : "r"(addr));
}
__device__ __forceinline__ void mma_f16(float* d, const uint32_t* a,
                                        const uint32_t* b) {
    asm volatile(
        "mma.sync.aligned.m16n8k16.row.col.f32.f16.f16.f32 "
        "{%0,%1,%2,%3}, {%4,%5,%6,%7}, {%8,%9}, {%0,%1,%2,%3};"
        : "+f"(d[0]), "+f"(d[1]), "+f"(d[2]), "+f"(d[3])
        : "r"(a[0]), "r"(a[1]), "r"(a[2]), "r"(a[3]), "r"(b[0]), "r"(b[1]));
}
// 128B-row swizzle (8 x 16B units): unit ^= row&7  (validated rounds 5-6)
__device__ __forceinline__ uint32_t sw_addr(uint32_t base, int row, int unit) {
    return base + row * 128 + (((unit) ^ (row & 7)) << 4);
}
__device__ __forceinline__ void cp_async16(uint32_t saddr, const void* gptr,
                                           uint32_t bytes) {
    asm volatile("cp.async.cg.shared.global [%0], [%1], 16, %2;"
                 :: "r"(saddr), "l"(gptr), "r"(bytes) : "memory");
}
#define CP_COMMIT() asm volatile("cp.async.commit_group;" ::: "memory")
#define CP_WAIT1()  asm volatile("cp.async.wait_group 1;" ::: "memory")
#define CP_WAIT0()  asm volatile("cp.async.wait_group 0;" ::: "memory")

// ------------------------- f32x2 helpers (final_gemm) ----------------------
__device__ __forceinline__ u64 pack2(float lo, float hi) {
    u64 r; asm("mov.b64 %0,{%1,%2};" : "=l"(r) : "f"(lo), "f"(hi)); return r;
}
__device__ __forceinline__ float2 unpack2(u64 v) {
    float2 f; asm("mov.b64 {%0,%1},%2;" : "=f"(f.x), "=f"(f.y) : "l"(v)); return f;
}
__device__ __forceinline__ u64 fma2(u64 a, u64 b, u64 c) {
    u64 d; asm("fma.rn.f32x2 %0,%1,%2,%3;" : "=l"(d) : "l"(a), "l"(b), "l"(c)); return d;
}

// ------------------------- device scratch ----------------------------------
__device__ float g_Wqkv[384 * 128];
__device__ float g_Wdw[384 * 384 * 9];
__device__ float g_Wpo[128 * 128];
__device__ __half g_Weff16[384 * 1152];          // [o][tap*128+c]
__device__ float g_tb[384 * 9];
__device__ __half g_xt16[2 * SPATIAL * 128];     // [b][s][c]
__device__ float g_qkv2[2 * 384 * SPATIAL];
__device__ float g_attnP[2 * 4 * 32 * 32];
__device__ float g_attn[2 * 4 * 32 * 32];
__device__ float g_inv[2 * 2 * 128];
__device__ float g_ss[2 * 256];
__device__ float g_M2[2 * 128 * 128];

// ---------------------------------------------------------------------------
// P1: transpose x to [b][s][c] fp16; block(0,0) also zeros scratch.
// ---------------------------------------------------------------------------
__global__ void prep_x(const float* __restrict__ X) {
    __shared__ float t[128][33];
    int s0 = blockIdx.x * 32;
    int b  = blockIdx.y;
    int tid = threadIdx.x;

    if (blockIdx.x == 0 && b == 0) {
        for (int i = tid; i < 8192; i += 256) g_attnP[i] = 0.f;
        for (int i = tid; i < 512; i += 256) g_ss[i] = 0.f;
    }
    for (int i = tid; i < 4096; i += 256) {
        int c = i >> 5, s = i & 31;
        t[c][s] = X[((size_t)(b * 128 + c)) * SPATIAL + s0 + s];
    }
    __syncthreads();
    for (int i = tid; i < 4096; i += 256) {
        int s = i >> 7, c = i & 127;
        g_xt16[((size_t)b * SPATIAL + s0 + s) * 128 + c] = __float2half(t[c][s]);
    }
}

// ---------------------------------------------------------------------------
// P2: Hamilton-product block expansion.
// ---------------------------------------------------------------------------
__global__ void expand_hamilton(const float* __restrict__ r,
                                const float* __restrict__ i_,
                                const float* __restrict__ j_,
                                const float* __restrict__ k_,
                                int dest, int O4, int C4, int T) {
    int idx = blockIdx.x * blockDim.x + threadIdx.x;
    int total = 16 * O4 * C4 * T;
    if (idx >= total) return;

    int tap = idx % T;
    int rem = idx / T;
    int C = 4 * C4;
    int c = rem % C;
    int o = rem / C;
    int br = o / O4, oo = o % O4;
    int bc = c / C4, cc = c % C4;

    const int   src[16] = {0,1,2,3, 1,0,3,2, 2,3,0,1, 3,2,1,0};
    const float sgn[16] = {1.f,-1.f,-1.f,-1.f, 1.f,1.f,-1.f,1.f,
                           1.f,1.f,1.f,-1.f,  1.f,-1.f,1.f,1.f};
    const float* comp[4] = {r, i_, j_, k_};

    float v = sgn[br * 4 + bc] * comp[src[br * 4 + bc]][(oo * C4 + cc) * T + tap];
    if (dest == 0) g_Wqkv[idx] = v;
    else if (dest == 1) g_Wdw[idx] = v;
    else g_Wpo[idx] = v;
}

// ---------------------------------------------------------------------------
// P3: Weff per output row -> fp16 at [o][tap*128+c]; tb fold.
// ---------------------------------------------------------------------------
__global__ __launch_bounds__(128)
void weff_o(const float* __restrict__ qkv_b) {
    int o = blockIdx.x;
    int c = threadIdx.x;

    __shared__ float wdw_s[288 + 8];
    __shared__ float wq_s[32 * 128];
    __shared__ float qb_s[384];

    for (int m = c; m < 384; m += 128) qb_s[m] = qkv_b[m];

    float acc[9], tbp[9];
#pragma unroll
    for (int t = 0; t < 9; ++t) { acc[t] = 0.f; tbp[t] = 0.f; }

    const float* wdw_row = g_Wdw + (size_t)o * 3456;

    for (int cb = 0; cb < 12; ++cb) {
        __syncthreads();
        for (int i = c; i < 288; i += 128)
            wdw_s[i] = wdw_row[cb * 288 + i];
        for (int i = c; i < 4096; i += 128) {
            int m = i >> 7, col = i & 127;
            wq_s[m * 128 + col] = g_Wqkv[(cb * 32 + m) * 128 + col];
        }
        __syncthreads();
#pragma unroll 4
        for (int m = 0; m < 32; ++m) {
            float wq = wq_s[m * 128 + c];
#pragma unroll
            for (int t = 0; t < 9; ++t)
                acc[t] = fmaf(wdw_s[m * 9 + t], wq, acc[t]);
        }
        if (c < 32) {
            float qb = qb_s[cb * 32 + c];
#pragma unroll
            for (int t = 0; t < 9; ++t)
                tbp[t] = fmaf(wdw_s[c * 9 + t], qb, tbp[t]);
        }
    }

#pragma unroll
    for (int t = 0; t < 9; ++t)
        g_Weff16[(size_t)o * 1152 + t * 128 + c] = __float2half(acc[t]);

    if (c < 32) {
#pragma unroll
        for (int t = 0; t < 9; ++t) {
            float v = tbp[t];
#pragma unroll
            for (int off = 16; off; off >>= 1)
                v += __shfl_xor_sync(0xffffffffu, v, off);
            if (c == 0) g_tb[o * 9 + t] = v;
        }
    }
}

// ---------------------------------------------------------------------------
// P4: conv via mma.sync fp16 single pass, 2-stage cp.async pipeline.
// CTA = M128 x N128 (one image row y). 8 warps 2(M)x4(N); warp tile 64x32.
// K: 9 taps x 2 chunks of 64 ch = 18 iterations x 4 k16-steps.
// Stage: A [128][64] fp16 16KB + B [128][64] fp16 16KB = 32KB; x2 = 64KB.
// ---------------------------------------------------------------------------
#define ST_A 0
#define ST_B (16 * 1024)
#define STAGE_BYTES (32 * 1024)
#define CONV_SMEM (2 * STAGE_BYTES)

__device__ __forceinline__ void conv_fill(uint32_t sbase, int tid,
                                          int it, int y, int o0, int b) {
    int tap = it >> 1;
    int ch  = (it & 1) * 64;
    int dy = tap / 3 - 1, dx = tap % 3 - 1;
    uint32_t stg = sbase + (it & 1) * STAGE_BYTES;

    // A: [128 o][64 k] = 1024 x 16B
    for (int i = tid; i < 1024; i += 256) {
        int row = i >> 3, u = i & 7;
        const __half* src = g_Weff16 +
            (size_t)(o0 + row) * 1152 + tap * 128 + ch + u * 8;
        cp_async16(sw_addr(stg + ST_A, row, u), src, 16u);
    }
    // B: [128 n][64 k] = 1024 x 16B, (dy,dx)-gathered, zero halo
    int yy = y + dy;
    bool yok = (unsigned)yy < 128u;
    for (int i = tid; i < 1024; i += 256) {
        int n = i >> 3, u = i & 7;
        int xx = n + dx;
        bool ok = yok && ((unsigned)xx < 128u);
        const __half* src = ok
            ? g_xt16 + ((size_t)b * SPATIAL + yy * 128 + xx) * 128 + ch + u * 8
            : g_xt16;
        cp_async16(sw_addr(stg + ST_B, n, u), src, ok ? 16u : 0u);
    }
    CP_COMMIT();
}

__global__ __launch_bounds__(256)
void conv_mma(const float* __restrict__ dwb) {
    extern __shared__ char smem[];
    uint32_t sbase = smem_to_u32(smem);
    int tid = threadIdx.x, wid = tid >> 5, lane = tid & 31;
    int y  = blockIdx.x;          // image row
    int o0 = blockIdx.y * 128;    // output-channel tile
    int b  = blockIdx.z;

    int warpM = wid >> 2;         // 0..1 -> 64 chans
    int warpN = wid & 3;          // 0..3 -> 32 pixels
    int lm = lane >> 3;
    int r8 = lane & 7;

    float acc[4][4][4];
#pragma unroll
    for (int mt = 0; mt < 4; ++mt)
#pragma unroll
        for (int nt = 0; nt < 4; ++nt)
#pragma unroll
            for (int q = 0; q < 4; ++q) acc[mt][nt][q] = 0.f;

    conv_fill(sbase, tid, 0, y, o0, b);
    conv_fill(sbase, tid, 1, y, o0, b);

    for (int it = 0; it < 18; ++it) {
        if (it < 16) CP_WAIT1(); else CP_WAIT0();
        __syncthreads();

        uint32_t stg = sbase + (it & 1) * STAGE_BYTES;
        uint32_t sA = stg + ST_A, sB = stg + ST_B;

#pragma unroll
        for (int ks = 0; ks < 4; ++ks) {
            uint32_t bf[8];
#pragma unroll
            for (int p = 0; p < 2; ++p) {
                int rowB = warpN * 32 + p * 16 + ((lm >> 1) << 3) + r8;
                int unitB = ks * 2 + (lm & 1);
                ldsm4(&bf[p * 4], sw_addr(sB, rowB, unitB));
            }
#pragma unroll
            for (int mt = 0; mt < 4; ++mt) {
                int rowA = warpM * 64 + mt * 16 + ((lm & 1) << 3) + r8;
                int unitA = ks * 2 + (lm >> 1);
                uint32_t af[4];
                ldsm4(af, sw_addr(sA, rowA, unitA));
#pragma unroll
                for (int nt = 0; nt < 4; ++nt)
                    mma_f16(acc[mt][nt], af, &bf[nt * 2]);
            }
        }
        __syncthreads();
        if (it + 2 < 18)
            conv_fill(sbase, tid, it + 2, y, o0, b);
    }

    // bias triple per local o into smem
    float* bias_s = (float*)smem;   // [128][3]
    if (tid < 128) {
        int o = o0 + tid;
        const float* t = &g_tb[o * 9];
        float f0 = (y >= 1) ? 1.f : 0.f;
        float f2 = (y <= 126) ? 1.f : 0.f;
        bias_s[tid * 3 + 0] = dwb[o] + f0 * t[1] + t[4] + f2 * t[7];
        bias_s[tid * 3 + 1] = f0 * t[0] + t[3] + f2 * t[6];
        bias_s[tid * 3 + 2] = f0 * t[2] + t[5] + f2 * t[8];
    }
    __syncthreads();

    int rr = lane >> 2;
    int q2 = (lane & 3) * 2;
    bool doss = (o0 < 256);
#pragma unroll
    for (int mt = 0; mt < 4; ++mt) {
#pragma unroll
        for (int half = 0; half < 2; ++half) {
            int o_loc = warpM * 64 + mt * 16 + rr + half * 8;
            int o = o0 + o_loc;
            float base = bias_s[o_loc * 3 + 0];
            float rs0  = bias_s[o_loc * 3 + 1];
            float rs2  = bias_s[o_loc * 3 + 2];
            float ss = 0.f;
            float* dst = g_qkv2 + (size_t)(b * 384 + o) * SPATIAL + y * 128;
#pragma unroll
            for (int nt = 0; nt < 4; ++nt) {
                int x = warpN * 32 + nt * 8 + q2;
                float v0 = acc[mt][nt][half * 2 + 0] + base + rs2;
                if (x >= 1) v0 += rs0;
                float v1 = acc[mt][nt][half * 2 + 1] + base + rs0;
                if (x + 1 <= 126) v1 += rs2;
                *(float2*)(dst + x) = make_float2(v0, v1);
                ss = fmaf(v0, v0, ss);
                ss = fmaf(v1, v1, ss);
            }
            ss += __shfl_xor_sync(0xffffffffu, ss, 1);
            ss += __shfl_xor_sync(0xffffffffu, ss, 2);
            if (doss && (lane & 3) == 0)
                atomicAdd(&g_ss[b * 256 + o], ss);
        }
    }
}

// ---------------------------------------------------------------------------
// P5: finish inverse norms.
// ---------------------------------------------------------------------------
__global__ void norms_finish() {
    int r = blockIdx.x * 256 + threadIdx.x;
    if (r >= 512) return;
    int qk = r >> 8;
    int b  = (r >> 7) & 1;
    int ch = r & 127;
    float ss = g_ss[b * 256 + qk * 128 + ch];
    g_inv[r] = 1.f / fmaxf(sqrtf(ss), 1e-12f);
}

// ---------------------------------------------------------------------------
// P6: attn partial sums (32 K-slices x 8 bh, atomics).
// ---------------------------------------------------------------------------
__global__ void attn_partial() {
    int slice = blockIdx.x;
    int bh = blockIdx.y;
    int b = bh >> 2, h = bh & 3;
    const float* qb = g_qkv2 + (size_t)(b * 384 + h * 32) * SPATIAL;
    const float* kb = g_qkv2 + (size_t)(b * 384 + 128 + h * 32) * SPATIAL;

    __shared__ float qs[32][65], ks[32][65];
    int tid = threadIdx.x;
    int c = tid >> 3;
    int d0 = (tid & 7) * 4;
    float acc[4] = {0.f, 0.f, 0.f, 0.f};

    for (int sub = 0; sub < 8; ++sub) {
        int s0 = slice * 512 + sub * 64;
        for (int i = tid; i < 2048; i += 256) {
            int cc = i >> 6, kk = i & 63;
            qs[cc][kk] = qb[(size_t)cc * SPATIAL + s0 + kk];
            ks[cc][kk] = kb[(size_t)cc * SPATIAL + s0 + kk];
        }
        __syncthreads();
#pragma unroll 8
        for (int kk = 0; kk < 64; ++kk) {
            float qv = qs[c][kk];
#pragma unroll
            for (int j = 0; j < 4; ++j)
                acc[j] = fmaf(qv, ks[d0 + j][kk], acc[j]);
        }
        __syncthreads();
    }
#pragma unroll
    for (int j = 0; j < 4; ++j)
        atomicAdd(&g_attnP[(bh * 32 + c) * 32 + d0 + j], acc[j]);
}

// ---------------------------------------------------------------------------
// P7: softmax with inv-norms and temperature fused in.
// ---------------------------------------------------------------------------
__global__ void softmax_kernel(const float* __restrict__ temp) {
    int row = blockIdx.x;
    int bh = row >> 5, c = row & 31;
    int b = bh >> 2, h = bh & 3;
    int d = threadIdx.x;

    float invq = g_inv[b * 128 + h * 32 + c];
    float invk = g_inv[256 + b * 128 + h * 32 + d];
    float v = g_attnP[row * 32 + d] * invq * invk * temp[h];

    float mx = v;
#pragma unroll
    for (int off = 16; off; off >>= 1)
        mx = fmaxf(mx, __shfl_xor_sync(0xffffffffu, mx, off));
    float e = expf(v - mx);
    float s = e;
#pragma unroll
    for (int off = 16; off; off >>= 1)
        s += __shfl_xor_sync(0xffffffffu, s, off);
    g_attn[row * 32 + d] = e / s;
}

// ---------------------------------------------------------------------------
// P8: M2[b][o][h*32+d] = sum_c Wpo[o][h*32+c] * attn[bh][c][d]
// ---------------------------------------------------------------------------
__global__ void make_M2() {
    int b = blockIdx.x, h = blockIdx.y;
    int bh = b * 4 + h;
    int tid = threadIdx.x;

    __shared__ float A[32][33];
    __shared__ float W[128][33];

    for (int i = tid; i < 1024; i += 256) {
        int c = i >> 5, d = i & 31;
        A[c][d] = g_attn[(bh * 32 + c) * 32 + d];
    }
    for (int i = tid; i < 4096; i += 256) {
        int o = i >> 5, c = i & 31;
        W[o][c] = g_Wpo[o * 128 + h * 32 + c];
    }
    __syncthreads();

    int o = tid >> 1;
    int d0 = (tid & 1) * 16;
#pragma unroll
    for (int dd = 0; dd < 16; ++dd) {
        int d = d0 + dd;
        float s = 0.f;
#pragma unroll
        for (int c = 0; c < 32; ++c)
            s = fmaf(W[o][c], A[c][d], s);
        g_M2[b * 16384 + o * 128 + h * 32 + d] = s;
    }
}

// ---------------------------------------------------------------------------
// P9: out[b][o][s] = sum_dg M2[b][o][dg] * v[b][dg][s] + po_b[o]  (fp32x2)
// ---------------------------------------------------------------------------
__global__ __launch_bounds__(256)
void final_gemm(const float* __restrict__ pob, float* __restrict__ out) {
    int s0 = blockIdx.x * 128;
    int b  = blockIdx.z;
    int tid = threadIdx.x;
    int tr = tid >> 4, tc = tid & 15;

    __shared__ float As[16][128];
    __shared__ float Bs[16][132];

    u64 acc2[4][8];
#pragma unroll
    for (int mp = 0; mp < 4; ++mp)
#pragma unroll
        for (int n = 0; n < 8; ++n) acc2[mp][n] = 0ull;

    for (int cb = 0; cb < 8; ++cb) {
        for (int i = tid; i < 2048; i += 256) {
            int o = i >> 4, kk = i & 15;
            As[kk][o] = g_M2[b * 16384 + o * 128 + cb * 16 + kk];
        }
        for (int i = tid; i < 2048; i += 256) {
            int kk = i >> 7, sx = i & 127;
            Bs[kk][sx] = g_qkv2[(size_t)(b * 384 + 256 + cb * 16 + kk) * SPATIAL + s0 + sx];
        }
        __syncthreads();
#pragma unroll
        for (int kk = 0; kk < 16; ++kk) {
            u64 a2[4];
#pragma unroll
            for (int mp = 0; mp < 4; ++mp)
                a2[mp] = *(const u64*)&As[kk][tr * 8 + 2 * mp];
            const float* brow = &Bs[kk][tc * 8];
            float4 w0 = *(const float4*)brow;
            float4 w1 = *(const float4*)(brow + 4);
            u64 bb[8];
            bb[0] = pack2(w0.x, w0.x); bb[1] = pack2(w0.y, w0.y);
            bb[2] = pack2(w0.z, w0.z); bb[3] = pack2(w0.w, w0.w);
            bb[4] = pack2(w1.x, w1.x); bb[5] = pack2(w1.y, w1.y);
            bb[6] = pack2(w1.z, w1.z); bb[7] = pack2(w1.w, w1.w);
#pragma unroll
            for (int mp = 0; mp < 4; ++mp)
#pragma unroll
                for (int n = 0; n < 8; ++n)
                    acc2[mp][n] = fma2(a2[mp], bb[n], acc2[mp][n]);
        }
        __syncthreads();
    }

#pragma unroll
    for (int mp = 0; mp < 4; ++mp) {
        int oA = tr * 8 + 2 * mp;
        float b0 = pob[oA], b1 = pob[oA + 1];
        float* op0 = out + (size_t)(b * 128 + oA) * SPATIAL + s0 + tc * 8;
        float* op1 = op0 + SPATIAL;
#pragma unroll
        for (int n = 0; n < 8; ++n) {
            float2 v = unpack2(acc2[mp][n]);
            op0[n] = v.x + b0;
            op1[n] = v.y + b1;
        }
    }
}

// ---------------------------------------------------------------------------
extern "C" void kernel_launch(void* const* d_in, const int* in_sizes, int n_in,
                              void* d_out, int out_size) {
    const float* x     = (const float*)d_in[0];
    const float* qkv_r = (const float*)d_in[1];
    const float* qkv_i = (const float*)d_in[2];
    const float* qkv_j = (const float*)d_in[3];
    const float* qkv_k = (const float*)d_in[4];
    const float* qkv_b = (const float*)d_in[5];
    const float* dw_r  = (const float*)d_in[6];
    const float* dw_i  = (const float*)d_in[7];
    const float* dw_j  = (const float*)d_in[8];
    const float* dw_k  = (const float*)d_in[9];
    const float* dw_b  = (const float*)d_in[10];
    const float* po_r  = (const float*)d_in[11];
    const float* po_i  = (const float*)d_in[12];
    const float* po_j  = (const float*)d_in[13];
    const float* po_k  = (const float*)d_in[14];
    const float* po_b  = (const float*)d_in[15];
    const float* temp  = (const float*)d_in[16];
    float* out = (float*)d_out;

    cudaFuncSetAttribute(conv_mma, cudaFuncAttributeMaxDynamicSharedMemorySize,
                         CONV_SMEM);

    // launches 1..5 (conv is the 6th for ncu -s 5 -c 1)
    prep_x<<<dim3(512, 2), 256>>>(x);
    expand_hamilton<<<192, 256>>>(qkv_r, qkv_i, qkv_j, qkv_k, 0, 96, 32, 1);
    expand_hamilton<<<5184, 256>>>(dw_r, dw_i, dw_j, dw_k, 1, 96, 96, 9);
    expand_hamilton<<<64, 256>>>(po_r, po_i, po_j, po_k, 2, 32, 32, 1);
    weff_o<<<384, 128>>>(qkv_b);

    // launch 6: single-pass fp16 HMMA conv
    conv_mma<<<dim3(128, 3, 2), 256, CONV_SMEM>>>(dw_b);

    // attention tail
    norms_finish<<<2, 256>>>();
    attn_partial<<<dim3(32, 8), 256>>>();
    softmax_kernel<<<256, 32>>>(temp);
    make_M2<<<dim3(2, 4), 256>>>();
    final_gemm<<<dim3(128, 1, 2), 256>>>(po_b, out);
}